// round 6
// baseline (speedup 1.0000x reference)
#include <cuda_runtime.h>
#include <cuda_bf16.h>
#include <cstdint>

// TorchBiRNN: B=64, T=512, I=128, H=256 bidirectional tanh RNN.
// Phase 1: pre[d][t][b][h] = x[b][t][:]·w_ih_d[h][:] + b_ih_d[h] + b_hh_d[h]
// Phase 2: 64 clusters x 2 CTAs. k-split by ORIGIN: c=0 threads dot the
//          locally-produced h half (no peer wait), c=1 threads dot the peer
//          half (only they wait on a remote-only, count=4 mbarrier). c1 does
//          the epilogue; warp-aggregated release-arrive to the peer.

#define OUT_YS (64 * 512 * 512)

__device__ float g_pre[2 * 512 * 64 * 256];   // 64 MB scratch (module-static)

// ---------------- helpers ----------------
__device__ __forceinline__ unsigned long long ffma2(unsigned long long a,
                                                    unsigned long long b,
                                                    unsigned long long c) {
    unsigned long long d;
    asm("fma.rn.f32x2 %0, %1, %2, %3;" : "=l"(d) : "l"(a), "l"(b), "l"(c));
    return d;
}
__device__ __forceinline__ unsigned long long pack2(float a, float b) {
    unsigned long long r;
    asm("mov.b64 %0, {%1, %2};" : "=l"(r) : "f"(a), "f"(b));
    return r;
}
__device__ __forceinline__ float sum2(unsigned long long v) {
    float2 f;
    asm("mov.b64 {%0, %1}, %2;" : "=f"(f.x), "=f"(f.y) : "l"(v));
    return f.x + f.y;
}
__device__ __forceinline__ uint32_t s2u(const void* p) {
    return (uint32_t)__cvta_generic_to_shared((void*)p);
}
__device__ __forceinline__ float fast_tanh(float x) {
    float e = __expf(2.0f * x);
    return 1.0f - __fdividef(2.0f, e + 1.0f);
}

#define MBAR_WAIT(addr, par)                                                    \
    asm volatile(                                                               \
        "{ .reg .pred P;\n"                                                     \
        "W_%=:\n"                                                               \
        " mbarrier.try_wait.parity.acquire.cluster.shared::cta.b64 P, [%0], %1;\n" \
        " @!P bra W_%=;\n"                                                      \
        "}" :: "r"(addr), "r"(par) : "memory")

// ---------------------------------------------------------------------------
// Phase 1: GEMM. M=32768 (m = t*64+b), N=256, K=128 staged by 64.
// 64x64 tile, 256 threads, 4x4 microtile, FFMA2, XOR-swizzled smem.
// ---------------------------------------------------------------------------
__global__ __launch_bounds__(256, 2) void pre_gemm_kernel(
    const float* __restrict__ x,
    const float* __restrict__ w_ih_f, const float* __restrict__ b_ih_f,
    const float* __restrict__ b_hh_f,
    const float* __restrict__ w_ih_b, const float* __restrict__ b_ih_b,
    const float* __restrict__ b_hh_b)
{
    __shared__ __align__(16) float4 xs4[64][16];
    __shared__ __align__(16) float4 ws4[64][16];

    const int bx = blockIdx.x;
    const int d  = bx >> 11;
    const int mt = (bx & 2047) >> 2;
    const int nt = bx & 3;
    const float* __restrict__ w_ih = d ? w_ih_b : w_ih_f;
    const float* __restrict__ bi   = d ? b_ih_b : b_ih_f;
    const float* __restrict__ bh   = d ? b_hh_b : b_hh_f;
    const int m0 = mt << 6, n0 = nt << 6;
    const int tid = threadIdx.x;
    const int tm = tid & 15, tn = tid >> 4;

    unsigned long long acc[4][4];
#pragma unroll
    for (int m = 0; m < 4; m++)
#pragma unroll
        for (int n = 0; n < 4; n++) acc[m][n] = 0ull;

#pragma unroll
    for (int ks = 0; ks < 128; ks += 64) {
#pragma unroll
        for (int i = 0; i < 4; i++) {
            int idx = tid + (i << 8);
            int r = idx >> 4, c4 = idx & 15;
            int sw = c4 ^ ((r >> 2) & 7);
            int m = m0 + r;
            int t = m >> 6, b = m & 63;
            xs4[r][sw] = *(const float4*)(x + ((size_t)(b << 9) + t) * 128 + ks + (c4 << 2));
            ws4[r][sw] = *(const float4*)(w_ih + ((size_t)(n0 + r) << 7) + ks + (c4 << 2));
        }
        __syncthreads();
#pragma unroll
        for (int k4 = 0; k4 < 16; k4++) {
            ulonglong2 a2[4], b2[4];
#pragma unroll
            for (int m = 0; m < 4; m++)
                a2[m] = *(const ulonglong2*)&xs4[(tm << 2) + m][k4 ^ (tm & 7)];
#pragma unroll
            for (int n = 0; n < 4; n++)
                b2[n] = *(const ulonglong2*)&ws4[(tn << 2) + n][k4 ^ (tn & 7)];
#pragma unroll
            for (int m = 0; m < 4; m++)
#pragma unroll
                for (int n = 0; n < 4; n++) {
                    acc[m][n] = ffma2(a2[m].x, b2[n].x, acc[m][n]);
                    acc[m][n] = ffma2(a2[m].y, b2[n].y, acc[m][n]);
                }
        }
        __syncthreads();
    }

    const int nbase = n0 + (tn << 2);
    float4 bi4 = *(const float4*)(bi + nbase);
    float4 bh4 = *(const float4*)(bh + nbase);
    float4 bias;
    bias.x = bi4.x + bh4.x; bias.y = bi4.y + bh4.y;
    bias.z = bi4.z + bh4.z; bias.w = bi4.w + bh4.w;

#pragma unroll
    for (int m = 0; m < 4; m++) {
        int mrow = m0 + (tm << 2) + m;
        float4 o;
        o.x = sum2(acc[m][0]) + bias.x;
        o.y = sum2(acc[m][1]) + bias.y;
        o.z = sum2(acc[m][2]) + bias.z;
        o.w = sum2(acc[m][3]) + bias.w;
        *(float4*)(g_pre + ((size_t)(d * 32768 + mrow)) * 256 + nbase) = o;
    }
}

// ---------------------------------------------------------------------------
// Phase 2: recurrence. Grid 128, cluster (2,1,1), 256 threads.
// CTA id: half = id&1 (== ctarank), pair p = (id>>1)&31, dir d = id>>6.
// CTA owns rows [half*128, half*128+128) for batches (2p, 2p+1).
// Thread: j = tid&127 (row), c = tid>>7, R = half*128+j.
//   c==0: k over LOCAL h half [h0, h0+128)   — never waits on peer.
//   c==1: k over PEER  h half [h0^128, ...)  — waits on remote-only mbar(4),
//         then does the epilogue + DSMEM stores + warp-aggregated arrive.
// ---------------------------------------------------------------------------
__global__ __cluster_dims__(2, 1, 1) __launch_bounds__(256, 1)
void rnn_step_kernel(const float* __restrict__ w_hh_f,
                     const float* __restrict__ w_hh_b,
                     float* __restrict__ out)
{
    __shared__ __align__(16) float h_buf[2][2][256];   // [dbl][batch][256]
    __shared__ float red[2][128];
    __shared__ __align__(8) unsigned long long mbar;

    const int id   = blockIdx.x;
    const int half = id & 1;
    const int p    = (id >> 1) & 31;
    const int d    = id >> 6;
    const int b0   = 2 * p, b1 = 2 * p + 1;
    const int h0   = half << 7;
    const int peer = half ^ 1;

    const int tid = threadIdx.x;
    const int j   = tid & 127;
    const int c   = tid >> 7;
    const int R   = h0 + j;
    const int k0  = c ? (h0 ^ 128) : h0;   // origin-split k range

    const float* __restrict__ w_hh = d ? w_hh_b : w_hh_f;

    // weights for (row R, k in [k0, k0+128)) -> 64 ull regs
    unsigned long long w[64];
    {
        const float4* wp = (const float4*)(w_hh + (size_t)R * 256 + k0);
#pragma unroll
        for (int q = 0; q < 32; q++) {
            float4 v = wp[q];
            w[2 * q]     = pack2(v.x, v.y);
            w[2 * q + 1] = pack2(v.z, v.w);
        }
    }

    // zero initial h buffer 0 (both batches, full 256)
    ((float*)h_buf[0])[tid]       = 0.0f;
    ((float*)h_buf[0])[tid + 256] = 0.0f;

    const uint32_t mb = s2u(&mbar);
    if (tid == 0)
        asm volatile("mbarrier.init.shared.b64 [%0], 4;" :: "r"(mb) : "memory");
    __syncthreads();
    asm volatile("barrier.cluster.arrive.aligned;" ::: "memory");
    asm volatile("barrier.cluster.wait.aligned;" ::: "memory");

    const float* pre_base = g_pre + (size_t)d * (512 * 64 * 256);
    float pre0 = 0.f, pre1 = 0.f;
    if (c == 1) {               // epilogue lives on c==1 now
        int tt = d ? 511 : 0;
        pre0 = pre_base[((size_t)tt * 64 + b0) * 256 + R];
        pre1 = pre_base[((size_t)tt * 64 + b1) * 256 + R];
    }

    for (int s = 0; s < 512; s++) {
        const int cur = s & 1, nxt = cur ^ 1;
        const int t = d ? (511 - s) : s;

        float npre0 = 0.f, npre1 = 0.f;
        if (c == 1) {
            // prefetch next step's pre BEFORE the wait (LDG in flight)
            if (s < 511) {
                int tn2 = d ? (510 - s) : (s + 1);
                npre0 = pre_base[((size_t)tn2 * 64 + b0) * 256 + R];
                npre1 = pre_base[((size_t)tn2 * 64 + b1) * 256 + R];
            }
            if (s > 0) MBAR_WAIT(mb, (uint32_t)((s - 1) & 1));
        }

        // MAC: partial_b = sum over k in [k0,k0+128) of W[R][k]*h[b][k]
        unsigned long long a0 = 0ull, a1 = 0ull;
        const ulonglong2* hp0 = (const ulonglong2*)&h_buf[cur][0][k0];
        const ulonglong2* hp1 = (const ulonglong2*)&h_buf[cur][1][k0];
#pragma unroll
        for (int q = 0; q < 32; q++) {
            ulonglong2 hv0 = hp0[q];
            ulonglong2 hv1 = hp1[q];
            a0 = ffma2(w[2 * q],     hv0.x, a0);
            a0 = ffma2(w[2 * q + 1], hv0.y, a0);
            a1 = ffma2(w[2 * q],     hv1.x, a1);
            a1 = ffma2(w[2 * q + 1], hv1.y, a1);
        }
        float s0 = sum2(a0), s1 = sum2(a1);

        if (c == 0) {
            red[0][j] = s0;
            red[1][j] = s1;
            asm volatile("bar.arrive 1, 256;" ::: "memory");
        } else {
            asm volatile("bar.sync 1, 256;" ::: "memory");   // c0 arrived long ago
            float hv0 = fast_tanh(s0 + red[0][j] + pre0);
            float hv1 = fast_tanh(s1 + red[1][j] + pre1);
            // local h publish (visible to c0 via bottom __syncthreads)
            h_buf[nxt][0][R] = hv0;
            h_buf[nxt][1][R] = hv1;
            // peer h publish via DSMEM
            uint32_t a0u = s2u(&h_buf[nxt][0][R]);
            uint32_t a1u = s2u(&h_buf[nxt][1][R]);
            asm volatile("{ .reg .b32 ra; mapa.shared::cluster.u32 ra, %0, %1;"
                         " st.shared::cluster.f32 [ra], %2; }"
                         :: "r"(a0u), "r"(peer), "f"(hv0) : "memory");
            asm volatile("{ .reg .b32 ra; mapa.shared::cluster.u32 ra, %0, %1;"
                         " st.shared::cluster.f32 [ra], %2; }"
                         :: "r"(a1u), "r"(peer), "f"(hv1) : "memory");
            __syncwarp();
            if ((tid & 31) == 0) {   // one release-arrive per c1 warp -> count 4
                asm volatile("{ .reg .b32 ra; mapa.shared::cluster.u32 ra, %0, %1;"
                             " mbarrier.arrive.release.cluster.shared::cluster.b64 _, [ra]; }"
                             :: "r"(mb), "r"(peer) : "memory");
            }
            // global outputs: off the cross-CTA critical path
            out[(((size_t)b0 << 9) + t) * 512 + (d << 8) + R] = hv0;
            out[(((size_t)b1 << 9) + t) * 512 + (d << 8) + R] = hv1;
            if (s == 511) {
                out[OUT_YS + (((d << 6) + b0) << 8) + R] = hv0;
                out[OUT_YS + (((d << 6) + b1) << 8) + R] = hv1;
            }
            pre0 = npre0; pre1 = npre1;
        }
        __syncthreads();   // publish local h to c0; all reads of buf[cur] done
    }

    asm volatile("barrier.cluster.arrive.aligned;" ::: "memory");
    asm volatile("barrier.cluster.wait.aligned;" ::: "memory");
}

// ---------------------------------------------------------------------------
extern "C" void kernel_launch(void* const* d_in, const int* in_sizes, int n_in,
                              void* d_out, int out_size) {
    const float* x      = (const float*)d_in[0];
    const float* w_ih_f = (const float*)d_in[1];
    const float* w_hh_f = (const float*)d_in[2];
    const float* b_ih_f = (const float*)d_in[3];
    const float* b_hh_f = (const float*)d_in[4];
    const float* w_ih_b = (const float*)d_in[5];
    const float* w_hh_b = (const float*)d_in[6];
    const float* b_ih_b = (const float*)d_in[7];
    const float* b_hh_b = (const float*)d_in[8];
    float* out = (float*)d_out;

    pre_gemm_kernel<<<4096, 256>>>(x, w_ih_f, b_ih_f, b_hh_f,
                                   w_ih_b, b_ih_b, b_hh_b);
    rnn_step_kernel<<<128, 256>>>(w_hh_f, w_hh_b, out);
}

// round 7
// speedup vs baseline: 1.5130x; 1.5130x over previous
#include <cuda_runtime.h>
#include <cuda_bf16.h>
#include <cstdint>

// TorchBiRNN: B=64, T=512, I=128, H=256 bidirectional tanh RNN.
// Phase 1: pre[d][t][b][h] = x[b][t][:]·w_ih_d[h][:] + b_ih_d[h] + b_hh_d[h]
// Phase 2: CLUSTERLESS. 128 CTAs, one per (batch,dir) sequence. w_hh split:
//          192KB in registers (256 thr x 48 ull x 2 rows), 64KB streamed from
//          smem per step. Two __syncthreads per step, no mbarrier, no DSMEM.

#define OUT_YS (64 * 512 * 512)

__device__ float g_pre[2 * 512 * 64 * 256];   // 64 MB scratch (module-static)

// ---------------- helpers ----------------
__device__ __forceinline__ unsigned long long ffma2(unsigned long long a,
                                                    unsigned long long b,
                                                    unsigned long long c) {
    unsigned long long d;
    asm("fma.rn.f32x2 %0, %1, %2, %3;" : "=l"(d) : "l"(a), "l"(b), "l"(c));
    return d;
}
__device__ __forceinline__ unsigned long long pack2(float a, float b) {
    unsigned long long r;
    asm("mov.b64 %0, {%1, %2};" : "=l"(r) : "f"(a), "f"(b));
    return r;
}
__device__ __forceinline__ float sum2(unsigned long long v) {
    float2 f;
    asm("mov.b64 {%0, %1}, %2;" : "=f"(f.x), "=f"(f.y) : "l"(v));
    return f.x + f.y;
}
__device__ __forceinline__ float fast_tanh(float x) {
    float e = __expf(2.0f * x);
    return 1.0f - __fdividef(2.0f, e + 1.0f);
}

// ---------------------------------------------------------------------------
// Phase 1: GEMM. M=32768 (m = t*64+b), N=256, K=128 staged by 64.
// 64x64 tile, 256 threads, 4x4 microtile, FFMA2, XOR-swizzled smem.
// ---------------------------------------------------------------------------
__global__ __launch_bounds__(256, 2) void pre_gemm_kernel(
    const float* __restrict__ x,
    const float* __restrict__ w_ih_f, const float* __restrict__ b_ih_f,
    const float* __restrict__ b_hh_f,
    const float* __restrict__ w_ih_b, const float* __restrict__ b_ih_b,
    const float* __restrict__ b_hh_b)
{
    __shared__ __align__(16) float4 xs4[64][16];
    __shared__ __align__(16) float4 ws4[64][16];

    const int bx = blockIdx.x;
    const int d  = bx >> 11;
    const int mt = (bx & 2047) >> 2;
    const int nt = bx & 3;
    const float* __restrict__ w_ih = d ? w_ih_b : w_ih_f;
    const float* __restrict__ bi   = d ? b_ih_b : b_ih_f;
    const float* __restrict__ bh   = d ? b_hh_b : b_hh_f;
    const int m0 = mt << 6, n0 = nt << 6;
    const int tid = threadIdx.x;
    const int tm = tid & 15, tn = tid >> 4;

    unsigned long long acc[4][4];
#pragma unroll
    for (int m = 0; m < 4; m++)
#pragma unroll
        for (int n = 0; n < 4; n++) acc[m][n] = 0ull;

#pragma unroll
    for (int ks = 0; ks < 128; ks += 64) {
#pragma unroll
        for (int i = 0; i < 4; i++) {
            int idx = tid + (i << 8);
            int r = idx >> 4, c4 = idx & 15;
            int sw = c4 ^ ((r >> 2) & 7);
            int m = m0 + r;
            int t = m >> 6, b = m & 63;
            xs4[r][sw] = *(const float4*)(x + ((size_t)(b << 9) + t) * 128 + ks + (c4 << 2));
            ws4[r][sw] = *(const float4*)(w_ih + ((size_t)(n0 + r) << 7) + ks + (c4 << 2));
        }
        __syncthreads();
#pragma unroll
        for (int k4 = 0; k4 < 16; k4++) {
            ulonglong2 a2[4], b2[4];
#pragma unroll
            for (int m = 0; m < 4; m++)
                a2[m] = *(const ulonglong2*)&xs4[(tm << 2) + m][k4 ^ (tm & 7)];
#pragma unroll
            for (int n = 0; n < 4; n++)
                b2[n] = *(const ulonglong2*)&ws4[(tn << 2) + n][k4 ^ (tn & 7)];
#pragma unroll
            for (int m = 0; m < 4; m++)
#pragma unroll
                for (int n = 0; n < 4; n++) {
                    acc[m][n] = ffma2(a2[m].x, b2[n].x, acc[m][n]);
                    acc[m][n] = ffma2(a2[m].y, b2[n].y, acc[m][n]);
                }
        }
        __syncthreads();
    }

    const int nbase = n0 + (tn << 2);
    float4 bi4 = *(const float4*)(bi + nbase);
    float4 bh4 = *(const float4*)(bh + nbase);
    float4 bias;
    bias.x = bi4.x + bh4.x; bias.y = bi4.y + bh4.y;
    bias.z = bi4.z + bh4.z; bias.w = bi4.w + bh4.w;

#pragma unroll
    for (int m = 0; m < 4; m++) {
        int mrow = m0 + (tm << 2) + m;
        float4 o;
        o.x = sum2(acc[m][0]) + bias.x;
        o.y = sum2(acc[m][1]) + bias.y;
        o.z = sum2(acc[m][2]) + bias.z;
        o.w = sum2(acc[m][3]) + bias.w;
        *(float4*)(g_pre + ((size_t)(d * 32768 + mrow)) * 256 + nbase) = o;
    }
}

// ---------------------------------------------------------------------------
// Phase 2: recurrence. Grid 128 (one CTA per (batch,dir)), 256 threads.
// Thread (j = tid&127, c = tid>>7): rows {j, j+128}, k in [128c, 128c+128).
//   k[0:96)   of the window: weights in registers (48 ull per row).
//   k[96:128) of the window: weights in smem (float4 [c][r2][kq][j], 64KB).
// h quads are warp-uniform broadcast LDS. Epilogue parallel over all 256
// threads: c0 finishes row j (adds c1's partial), c1 finishes row j+128.
// Dynamic smem: ws4 64KB | h_buf 2x256 | redA 128 | redB 128  = 68608 B.
// ---------------------------------------------------------------------------
__global__ __launch_bounds__(256, 1)
void rnn_step_kernel(const float* __restrict__ w_hh_f,
                     const float* __restrict__ w_hh_b,
                     float* __restrict__ out)
{
    extern __shared__ __align__(16) char smem_raw[];
    float4* ws4   = (float4*)smem_raw;                    // [2][2][8][128]
    float*  h_buf = (float*)(smem_raw + 65536);           // [2][256]
    float*  redA  = h_buf + 512;                          // [128] c1 partials (row j)
    float*  redB  = redA + 128;                           // [128] c0 partials (row j+128)

    const int id  = blockIdx.x;
    const int d   = id >> 6;
    const int b   = id & 63;
    const int tid = threadIdx.x;
    const int j   = tid & 127;
    const int c   = tid >> 7;

    const float* __restrict__ w_hh = d ? w_hh_b : w_hh_f;

    // --- fill smem weights: ws4[((c*2+r2)*8+kq)*128 + j] = w[r2*128+j][c*128+96+4kq]
    for (int i = tid; i < 4096; i += 256) {
        int jj = i & 127, kq = (i >> 7) & 7, r2 = (i >> 10) & 1, cc = i >> 11;
        ws4[i] = *(const float4*)(w_hh + (size_t)((r2 << 7) + jj) * 256
                                       + (cc << 7) + 96 + (kq << 2));
    }

    // --- register weights: rows j and j+128, k in [128c, 128c+96)
    unsigned long long w0[48], w1[48];
    {
        const float4* p0 = (const float4*)(w_hh + (size_t)j * 256 + (c << 7));
        const float4* p1 = (const float4*)(w_hh + (size_t)(j + 128) * 256 + (c << 7));
#pragma unroll
        for (int q = 0; q < 24; q++) {
            float4 v0 = p0[q], v1 = p1[q];
            w0[2 * q]     = pack2(v0.x, v0.y);
            w0[2 * q + 1] = pack2(v0.z, v0.w);
            w1[2 * q]     = pack2(v1.x, v1.y);
            w1[2 * q + 1] = pack2(v1.z, v1.w);
        }
    }

    // zero initial h
    h_buf[tid] = 0.0f;          // buffer 0 = h_buf[0..255]
    __syncthreads();

    const float* pre_base = g_pre + (size_t)d * (512 * 64 * 256);
    const int myrow = c ? (j + 128) : j;     // row this thread finishes
    float pre_cur;
    {
        int t0 = d ? 511 : 0;
        pre_cur = pre_base[((size_t)t0 * 64 + b) * 256 + myrow];
    }

    const float4* wsc = ws4 + (c << 11) / 4 * 4;   // base for this c (1024 float4)
    const float4* ws_r0 = ws4 + ((c * 2 + 0) * 8) * 128 + j;
    const float4* ws_r1 = ws4 + ((c * 2 + 1) * 8) * 128 + j;

    for (int s = 0; s < 512; s++) {
        const int cur = s & 1, nxt = cur ^ 1;
        const int t = d ? (511 - s) : s;

        // prefetch next pre
        float pre_nxt = 0.0f;
        if (s < 511) {
            int t2 = d ? (510 - s) : (s + 1);
            pre_nxt = pre_base[((size_t)t2 * 64 + b) * 256 + myrow];
        }

        const ulonglong2* hb = (const ulonglong2*)(h_buf + (cur << 8) + (c << 7));

        unsigned long long a0 = 0ull, a1 = 0ull;
        // register-weight part: k-quads 0..23
#pragma unroll
        for (int q = 0; q < 24; q++) {
            ulonglong2 h2 = hb[q];
            a0 = ffma2(w0[2 * q],     h2.x, a0);
            a0 = ffma2(w0[2 * q + 1], h2.y, a0);
            a1 = ffma2(w1[2 * q],     h2.x, a1);
            a1 = ffma2(w1[2 * q + 1], h2.y, a1);
        }
        // smem-weight part: k-quads 24..31
#pragma unroll
        for (int kq = 0; kq < 8; kq++) {
            ulonglong2 h2 = hb[24 + kq];
            ulonglong2 wv0 = *(const ulonglong2*)&ws_r0[kq * 128];
            ulonglong2 wv1 = *(const ulonglong2*)&ws_r1[kq * 128];
            a0 = ffma2(wv0.x, h2.x, a0);
            a0 = ffma2(wv0.y, h2.y, a0);
            a1 = ffma2(wv1.x, h2.x, a1);
            a1 = ffma2(wv1.y, h2.y, a1);
        }
        float p0 = sum2(a0);       // partial for row j     (this c's k-window)
        float p1 = sum2(a1);       // partial for row j+128

        if (c == 0) redB[j] = p1; else redA[j] = p0;
        __syncthreads();

        float v = c ? (p1 + redB[j]) : (p0 + redA[j]);
        float hv = fast_tanh(v + pre_cur);
        h_buf[(nxt << 8) + myrow] = hv;
        out[(((size_t)b << 9) + t) * 512 + (d << 8) + myrow] = hv;
        if (s == 511)
            out[OUT_YS + (((d << 6) + b) << 8) + myrow] = hv;
        pre_cur = pre_nxt;
        __syncthreads();
    }
    (void)wsc;
}

// ---------------------------------------------------------------------------
extern "C" void kernel_launch(void* const* d_in, const int* in_sizes, int n_in,
                              void* d_out, int out_size) {
    const float* x      = (const float*)d_in[0];
    const float* w_ih_f = (const float*)d_in[1];
    const float* w_hh_f = (const float*)d_in[2];
    const float* b_ih_f = (const float*)d_in[3];
    const float* b_hh_f = (const float*)d_in[4];
    const float* w_ih_b = (const float*)d_in[5];
    const float* w_hh_b = (const float*)d_in[6];
    const float* b_ih_b = (const float*)d_in[7];
    const float* b_hh_b = (const float*)d_in[8];
    float* out = (float*)d_out;

    pre_gemm_kernel<<<4096, 256>>>(x, w_ih_f, b_ih_f, b_hh_f,
                                   w_ih_b, b_ih_b, b_hh_b);

    static bool attr_set = false;
    if (!attr_set) {
        cudaFuncSetAttribute(rnn_step_kernel,
                             cudaFuncAttributeMaxDynamicSharedMemorySize, 68608);
        attr_set = true;
    }
    rnn_step_kernel<<<128, 256, 68608>>>(w_hh_f, w_hh_b, out);
}